// round 5
// baseline (speedup 1.0000x reference)
#include <cuda_runtime.h>
#include <math.h>

#define HW   64
#define PIX  4096
#define BB   8
#define CC   512
#define NHH  8
#define HDD  64

// ---------------- scratch (device globals; no allocation) ----------------
__device__ float g_t1[(size_t)BB*64*PIX];        // box conv1 + GELU
__device__ float g_boxes[(size_t)BB*4*PIX];      // box net output (sigmoid)
__device__ float g_e1[(size_t)BB*64*PIX];        // edge conv1 (then GN+GELU in place)
__device__ float g_edge[(size_t)BB*NHH*PIX];     // edge net output
__device__ float g_qkv[(size_t)BB*1536*PIX];     // qkv conv output
__device__ float g_attn[(size_t)BB*NHH*HDD*PIX]; // attention logits / probs
__device__ float g_agg[(size_t)BB*CC*PIX];       // attention aggregation
__device__ float g_y[(size_t)BB*CC*PIX];         // fusion conv output (pre-BN)
__device__ float g_mean[CC];
__device__ float g_istd[CC];

__device__ __forceinline__ float gelu_exact(float x) {
    return 0.5f * x * (1.0f + erff(x * 0.70710678118654752440f));
}

// ---------------- generic conv3x3/1x1 as tiled implicit GEMM ----------------
// Block tile: 64 output channels x 256 pixels (4 rows of W=64).
// 256 threads, each computes 8 co x 8 px. 8-channel smem chunks.
// warp -> co group (weight LDS broadcast), lane -> pixel group.
template<int KS, bool CONCAT, int ACT>
__global__ __launch_bounds__(256) void conv_gemm(
    const float* __restrict__ in0, const float* __restrict__ in1,
    const float* __restrict__ wgt, const float* __restrict__ bias,
    float* __restrict__ out, int Cin, int C0, int Cout)
{
    constexpr int HALO = KS / 2;
    constexpr int SR = 4 + 2 * HALO;       // smem rows
    constexpr int SC = 64 + 2 * HALO;      // smem cols (valid)
    __shared__ float Xs[8][SR][66];        // stride 66 -> <=2-way conflicts
    __shared__ float Ws[64][8][KS * KS];

    const int tid  = threadIdx.x;
    const int warp = tid >> 5;
    const int lane = tid & 31;
    const int rloc = lane >> 3;            // 0..3 (pixel row within tile)
    const int c0   = (lane & 7) << 3;      // 0..56 (pixel col base)
    const int h0   = blockIdx.x * 4;
    const int cot  = blockIdx.y;
    const int b    = blockIdx.z;

    const float* base0 = in0 + (size_t)b * C0 * PIX;
    const float* base1 = CONCAT ? (in1 + (size_t)b * (Cin - C0) * PIX) : nullptr;

    float acc[8][8];
    #pragma unroll
    for (int a = 0; a < 8; a++)
        #pragma unroll
        for (int j = 0; j < 8; j++) acc[a][j] = 0.f;

    for (int cig = 0; cig < Cin; cig += 8) {
        // weights for this chunk
        const int WN = 64 * 8 * KS * KS;
        for (int idx = tid; idx < WN; idx += 256) {
            int col = idx / (8 * KS * KS);
            int rem = idx - col * (8 * KS * KS);
            int ci  = rem / (KS * KS);
            int t   = rem - ci * (KS * KS);
            Ws[col][ci][t] =
                wgt[((size_t)(cot * 64 + col) * Cin + (cig + ci)) * (KS * KS) + t];
        }
        // input tile (+halo, zero padded)
        const int XN = 8 * SR * SC;
        for (int idx = tid; idx < XN; idx += 256) {
            int ci  = idx / (SR * SC);
            int rem = idx - ci * (SR * SC);
            int r   = rem / SC;
            int ccx = rem - r * SC;
            int h   = h0 - HALO + r;
            int w   = ccx - HALO;
            float v = 0.f;
            if (h >= 0 && h < 64 && w >= 0 && w < 64) {
                int ch = cig + ci;
                const float* p = (CONCAT && ch >= C0)
                                     ? (base1 + (size_t)(ch - C0) * PIX)
                                     : (base0 + (size_t)ch * PIX);
                v = p[h * 64 + w];
            }
            Xs[ci][r][ccx] = v;
        }
        __syncthreads();

        #pragma unroll 1
        for (int ci = 0; ci < 8; ++ci) {
            #pragma unroll
            for (int ky = 0; ky < KS; ++ky) {
                #pragma unroll
                for (int kx = 0; kx < KS; ++kx) {
                    float wv[8], xv[8];
                    #pragma unroll
                    for (int j = 0; j < 8; j++)
                        wv[j] = Ws[warp * 8 + j][ci][ky * KS + kx];
                    #pragma unroll
                    for (int j = 0; j < 8; j++)
                        xv[j] = Xs[ci][rloc + ky][c0 + kx + j];
                    #pragma unroll
                    for (int a = 0; a < 8; a++)
                        #pragma unroll
                        for (int j = 0; j < 8; j++)
                            acc[a][j] = fmaf(wv[a], xv[j], acc[a][j]);
                }
            }
        }
        __syncthreads();
    }

    #pragma unroll
    for (int a = 0; a < 8; a++) {
        int co = cot * 64 + warp * 8 + a;
        float bv = bias[co];
        float* op = out + (((size_t)b * Cout + co) * 64 + (h0 + rloc)) * 64 + c0;
        #pragma unroll
        for (int j = 0; j < 8; j++) {
            float v = acc[a][j] + bv;
            if (ACT == 1) v = gelu_exact(v);
            op[j] = v;
        }
    }
}

// ---------------- box conv2 (64->4 1x1) + sigmoid ----------------
__global__ __launch_bounds__(256) void box_conv2(const float* __restrict__ w2,
                                                 const float* __restrict__ b2)
{
    __shared__ float ws[256];
    int tid = threadIdx.x;
    ws[tid] = w2[tid];                       // [4][64]
    __syncthreads();
    int b = blockIdx.y;
    int p = blockIdx.x * 256 + tid;
    const float* in = g_t1 + (size_t)b * 64 * PIX;
    float acc[4] = {b2[0], b2[1], b2[2], b2[3]};
    for (int ci = 0; ci < 64; ci++) {
        float xv = in[(size_t)ci * PIX + p];
        #pragma unroll
        for (int co = 0; co < 4; co++) acc[co] = fmaf(ws[co * 64 + ci], xv, acc[co]);
    }
    #pragma unroll
    for (int co = 0; co < 4; co++)
        g_boxes[((size_t)b * 4 + co) * PIX + p] = 1.0f / (1.0f + expf(-acc[co]));
}

// ---------------- edge conv1 (4->64 3x3) ----------------
__global__ __launch_bounds__(256) void edge_conv1(const float* __restrict__ w1,
                                                  const float* __restrict__ b1)
{
    __shared__ float ws[8][4][9];
    __shared__ float bs[8];
    int tid = threadIdx.x;
    int cg = blockIdx.x;                     // co group (8 channels)
    int b  = blockIdx.y;
    for (int idx = tid; idx < 288; idx += 256) {
        int j = idx / 36, rem = idx % 36;
        int ci = rem / 9, t = rem % 9;
        ws[j][ci][t] = w1[((cg * 8 + j) * 4 + ci) * 9 + t];
    }
    if (tid < 8) bs[tid] = b1[cg * 8 + tid];
    __syncthreads();
    const float* bx = g_boxes + (size_t)b * 4 * PIX;
    for (int px = tid; px < PIX; px += 256) {
        int h = px >> 6, w = px & 63;
        float acc[8];
        #pragma unroll
        for (int j = 0; j < 8; j++) acc[j] = bs[j];
        #pragma unroll
        for (int ky = 0; ky < 3; ky++) {
            int hh = h + ky - 1;
            if (hh < 0 || hh >= 64) continue;
            #pragma unroll
            for (int kx = 0; kx < 3; kx++) {
                int ww = w + kx - 1;
                if (ww < 0 || ww >= 64) continue;
                #pragma unroll
                for (int ci = 0; ci < 4; ci++) {
                    float xv = bx[(size_t)ci * PIX + hh * 64 + ww];
                    #pragma unroll
                    for (int j = 0; j < 8; j++)
                        acc[j] = fmaf(ws[j][ci][ky * 3 + kx], xv, acc[j]);
                }
            }
        }
        #pragma unroll
        for (int j = 0; j < 8; j++)
            g_e1[((size_t)b * 64 + cg * 8 + j) * PIX + px] = acc[j];
    }
}

// ---------------- GroupNorm(8,64) + GELU (in place on g_e1) ----------------
__global__ __launch_bounds__(256) void gn_gelu(const float* __restrict__ gam,
                                               const float* __restrict__ bet)
{
    int blk = blockIdx.x;
    int b = blk >> 3, g = blk & 7;
    float* buf = g_e1 + ((size_t)b * 64 + g * 8) * PIX;
    __shared__ float red[256], red2[256];
    __shared__ float sm, si;
    float s = 0.f, sq = 0.f;
    for (int t = threadIdx.x; t < 8 * PIX; t += 256) {
        float v = buf[t]; s += v; sq += v * v;
    }
    red[threadIdx.x] = s; red2[threadIdx.x] = sq;
    __syncthreads();
    for (int o = 128; o > 0; o >>= 1) {
        if (threadIdx.x < o) {
            red[threadIdx.x]  += red[threadIdx.x + o];
            red2[threadIdx.x] += red2[threadIdx.x + o];
        }
        __syncthreads();
    }
    if (threadIdx.x == 0) {
        float m = red[0] / (8.f * PIX);
        float var = red2[0] / (8.f * PIX) - m * m;
        sm = m; si = rsqrtf(var + 1e-5f);
    }
    __syncthreads();
    float m = sm, istd = si;
    for (int t = threadIdx.x; t < 8 * PIX; t += 256) {
        int cl = t >> 12;
        int c = g * 8 + cl;
        float v = (buf[t] - m) * istd * gam[c] + bet[c];
        buf[t] = gelu_exact(v);
    }
}

// ---------------- edge conv2 (64->8 1x1) ----------------
__global__ __launch_bounds__(256) void edge_conv2(const float* __restrict__ w2,
                                                  const float* __restrict__ b2)
{
    __shared__ float ws[512];
    int tid = threadIdx.x;
    ws[tid] = w2[tid];
    ws[tid + 256] = w2[tid + 256];
    __syncthreads();
    int b = blockIdx.y;
    int p = blockIdx.x * 256 + tid;
    const float* in = g_e1 + (size_t)b * 64 * PIX;
    float acc[8];
    #pragma unroll
    for (int co = 0; co < 8; co++) acc[co] = b2[co];
    for (int ci = 0; ci < 64; ci++) {
        float xv = in[(size_t)ci * PIX + p];
        #pragma unroll
        for (int co = 0; co < 8; co++) acc[co] = fmaf(ws[co * 64 + ci], xv, acc[co]);
    }
    #pragma unroll
    for (int co = 0; co < 8; co++)
        g_edge[((size_t)b * 8 + co) * PIX + p] = acc[co];
}

// ---------------- attention: S = scale*Q_i^T K_i + edge ----------------
__global__ __launch_bounds__(256) void attn_qk()
{
    __shared__ float Qs[64 * 64];
    __shared__ float Ks[64 * 64];
    int i = blockIdx.x, h = blockIdx.y, b = blockIdx.z;
    int tid = threadIdx.x;
    const float* qp = g_qkv + ((size_t)b * 1536 + h * 64 + i) * PIX;
    const float* kp = g_qkv + ((size_t)b * 1536 + 512 + h * 64 + i) * PIX;
    float4* Q4 = (float4*)Qs;
    float4* K4 = (float4*)Ks;
    for (int t = tid; t < 1024; t += 256) {
        Q4[t] = ((const float4*)qp)[t];
        K4[t] = ((const float4*)kp)[t];
    }
    __syncthreads();
    int wr = (tid >> 4) << 2;   // attn row (w) base
    int wc = (tid & 15) << 2;   // attn col (W') base
    float acc[4][4];
    #pragma unroll
    for (int a = 0; a < 4; a++)
        #pragma unroll
        for (int j = 0; j < 4; j++) acc[a][j] = 0.f;
    for (int d = 0; d < 64; d++) {
        float4 qv = Q4[d * 16 + (wr >> 2)];
        float4 kv = K4[d * 16 + (wc >> 2)];
        float q[4] = {qv.x, qv.y, qv.z, qv.w};
        float k[4] = {kv.x, kv.y, kv.z, kv.w};
        #pragma unroll
        for (int a = 0; a < 4; a++)
            #pragma unroll
            for (int j = 0; j < 4; j++)
                acc[a][j] = fmaf(q[a], k[j], acc[a][j]);
    }
    float* op = g_attn + ((size_t)(b * 8 + h) * 64 + i) * PIX;
    const float* ep = g_edge + (size_t)(b * 8 + h) * PIX + i * 64;
    #pragma unroll
    for (int a = 0; a < 4; a++) {
        float e = ep[wr + a];
        float4 o;
        o.x = acc[a][0] * 0.125f + e;
        o.y = acc[a][1] * 0.125f + e;
        o.z = acc[a][2] * 0.125f + e;
        o.w = acc[a][3] * 0.125f + e;
        *(float4*)(op + (wr + a) * 64 + wc) = o;
    }
}

// ---------------- softmax over i (HD axis) ----------------
__global__ __launch_bounds__(256) void attn_softmax()
{
    int w4 = blockIdx.x, h = blockIdx.y, b = blockIdx.z;
    int tid = threadIdx.x;
    int w  = w4 * 4 + (tid >> 6);
    int wp = tid & 63;
    float* base = g_attn + (size_t)(b * 8 + h) * 64 * PIX + w * 64 + wp;
    float v[64];
    #pragma unroll
    for (int i = 0; i < 64; i++) v[i] = base[(size_t)i * PIX];
    float m = v[0];
    #pragma unroll
    for (int i = 1; i < 64; i++) m = fmaxf(m, v[i]);
    float s = 0.f;
    #pragma unroll
    for (int i = 0; i < 64; i++) { v[i] = expf(v[i] - m); s += v[i]; }
    float r = 1.0f / s;
    #pragma unroll
    for (int i = 0; i < 64; i++) base[(size_t)i * PIX] = v[i] * r;
}

// ---------------- agg_i = V_i @ A_i^T ----------------
__global__ __launch_bounds__(256) void attn_agg()
{
    __shared__ float At[64 * 68];   // At[W][w] = attn[w][W]
    __shared__ float Vt[64 * 68];   // Vt[W][d] = v[d][W]
    int i = blockIdx.x, h = blockIdx.y, b = blockIdx.z;
    int tid = threadIdx.x;
    const float* ap = g_attn + ((size_t)(b * 8 + h) * 64 + i) * PIX;
    const float* vp = g_qkv + ((size_t)b * 1536 + 1024 + h * 64 + i) * PIX;
    for (int t = tid; t < 4096; t += 256) {
        int r = t >> 6, c = t & 63;
        At[c * 68 + r] = ap[t];
        Vt[c * 68 + r] = vp[t];
    }
    __syncthreads();
    int d0 = (tid >> 4) << 2;
    int w0 = (tid & 15) << 2;
    float acc[4][4];
    #pragma unroll
    for (int a = 0; a < 4; a++)
        #pragma unroll
        for (int j = 0; j < 4; j++) acc[a][j] = 0.f;
    for (int W = 0; W < 64; W++) {
        float4 vv = *(const float4*)(Vt + W * 68 + d0);
        float4 av = *(const float4*)(At + W * 68 + w0);
        float vd[4] = {vv.x, vv.y, vv.z, vv.w};
        float aw[4] = {av.x, av.y, av.z, av.w};
        #pragma unroll
        for (int a = 0; a < 4; a++)
            #pragma unroll
            for (int j = 0; j < 4; j++)
                acc[a][j] = fmaf(vd[a], aw[j], acc[a][j]);
    }
    float* op = g_agg + ((size_t)b * 512 + h * 64 + i) * PIX;
    #pragma unroll
    for (int a = 0; a < 4; a++) {
        float4 o = {acc[a][0], acc[a][1], acc[a][2], acc[a][3]};
        *(float4*)(op + (d0 + a) * 64 + w0) = o;
    }
}

// ---------------- BatchNorm stats (per channel over B,H,W) ----------------
__global__ __launch_bounds__(256) void bn_stats()
{
    int c = blockIdx.x;
    __shared__ float red[256], red2[256];
    float s = 0.f, sq = 0.f;
    for (int t = threadIdx.x; t < 8 * PIX; t += 256) {
        int b = t >> 12, p = t & 4095;
        float v = g_y[((size_t)b * 512 + c) * PIX + p];
        s += v; sq += v * v;
    }
    red[threadIdx.x] = s; red2[threadIdx.x] = sq;
    __syncthreads();
    for (int o = 128; o > 0; o >>= 1) {
        if (threadIdx.x < o) {
            red[threadIdx.x]  += red[threadIdx.x + o];
            red2[threadIdx.x] += red2[threadIdx.x + o];
        }
        __syncthreads();
    }
    if (threadIdx.x == 0) {
        float m = red[0] / (8.f * PIX);
        float var = red2[0] / (8.f * PIX) - m * m;
        g_mean[c] = m;
        g_istd[c] = rsqrtf(var + 1e-5f);
    }
}

// ---------------- BN apply + SiLU -> d_out ----------------
__global__ __launch_bounds__(256) void bn_silu(const float* __restrict__ gam,
                                               const float* __restrict__ bet,
                                               float* __restrict__ out)
{
    size_t idx = (size_t)blockIdx.x * 256 + threadIdx.x;
    int c = (int)((idx >> 12) & 511);
    float v = g_y[idx];
    float yn = (v - g_mean[c]) * g_istd[c] * gam[c] + bet[c];
    out[idx] = yn / (1.0f + expf(-yn));
}

// ---------------- launch ----------------
extern "C" void kernel_launch(void* const* d_in, const int* in_sizes, int n_in,
                              void* d_out, int out_size)
{
    const float* x       = (const float*)d_in[0];
    const float* box_w1  = (const float*)d_in[1];
    const float* box_b1  = (const float*)d_in[2];
    const float* box_w2  = (const float*)d_in[3];
    const float* box_b2  = (const float*)d_in[4];
    const float* edge_w1 = (const float*)d_in[5];
    const float* edge_b1 = (const float*)d_in[6];
    const float* gn_g    = (const float*)d_in[7];
    const float* gn_b    = (const float*)d_in[8];
    const float* edge_w2 = (const float*)d_in[9];
    const float* edge_b2 = (const float*)d_in[10];
    const float* qkv_w   = (const float*)d_in[11];
    const float* qkv_b   = (const float*)d_in[12];
    const float* fus_w   = (const float*)d_in[13];
    const float* fus_b   = (const float*)d_in[14];
    const float* bn_g    = (const float*)d_in[15];
    const float* bn_b    = (const float*)d_in[16];
    float* out = (float*)d_out;

    float *t1, *qkv, *agg, *y;
    cudaGetSymbolAddress((void**)&t1,  g_t1);
    cudaGetSymbolAddress((void**)&qkv, g_qkv);
    cudaGetSymbolAddress((void**)&agg, g_agg);
    cudaGetSymbolAddress((void**)&y,   g_y);

    // box net: conv3x3(512->64)+GELU, conv1x1(64->4)+sigmoid
    conv_gemm<3, false, 1><<<dim3(16, 1, 8), 256>>>(x, nullptr, box_w1, box_b1,
                                                    t1, 512, 512, 64);
    box_conv2<<<dim3(16, 8), 256>>>(box_w2, box_b2);

    // edge net: conv3x3(4->64), GN+GELU, conv1x1(64->8)
    edge_conv1<<<dim3(8, 8), 256>>>(edge_w1, edge_b1);
    gn_gelu<<<64, 256>>>(gn_g, gn_b);
    edge_conv2<<<dim3(16, 8), 256>>>(edge_w2, edge_b2);

    // qkv 1x1 conv (512->1536)
    conv_gemm<1, false, 0><<<dim3(16, 24, 8), 256>>>(x, nullptr, qkv_w, qkv_b,
                                                     qkv, 512, 512, 1536);

    // attention
    attn_qk<<<dim3(64, 8, 8), 256>>>();
    attn_softmax<<<dim3(16, 8, 8), 256>>>();
    attn_agg<<<dim3(64, 8, 8), 256>>>();

    // fusion conv3x3 (concat(x, agg): 1024->512)
    conv_gemm<3, true, 0><<<dim3(16, 8, 8), 256>>>(x, agg, fus_w, fus_b,
                                                   y, 1024, 512, 512);

    // BatchNorm (training stats) + SiLU
    bn_stats<<<512, 256>>>();
    bn_silu<<<65536, 256>>>(bn_g, bn_b, out);
}

// round 6
// speedup vs baseline: 2.5999x; 2.5999x over previous
#include <cuda_runtime.h>
#include <math.h>

#define HW   64
#define PIX  4096
#define BB   8
#define CC   512
#define NHH  8
#define HDD  64

// ---------------- scratch (device globals; no allocation) ----------------
__device__ float g_t1[(size_t)BB*64*PIX];        // box conv1 + GELU
__device__ float g_boxes[(size_t)BB*4*PIX];      // box net output (sigmoid)
__device__ float g_e1[(size_t)BB*64*PIX];        // edge conv1 (then GN+GELU in place)
__device__ float g_edge[(size_t)BB*NHH*PIX];     // edge net output
__device__ float g_qkv[(size_t)BB*1536*PIX];     // qkv conv output
__device__ float g_attn[(size_t)BB*NHH*HDD*PIX]; // attention logits / probs
__device__ float g_agg[(size_t)BB*CC*PIX];       // attention aggregation
__device__ float g_y[(size_t)BB*CC*PIX];         // fusion conv output (pre-BN)
__device__ float g_mean[CC];
__device__ float g_istd[CC];

__device__ __forceinline__ float gelu_exact(float x) {
    return 0.5f * x * (1.0f + erff(x * 0.70710678118654752440f));
}

__device__ __forceinline__ unsigned f2tf32(float f) {
    unsigned r;
    asm("cvt.rna.tf32.f32 %0, %1;" : "=r"(r) : "f"(f));
    return r;
}

__device__ __forceinline__ void mma_tf32(float* c, const unsigned* a, const unsigned* b) {
    asm volatile(
        "mma.sync.aligned.m16n8k8.row.col.f32.tf32.tf32.f32 "
        "{%0,%1,%2,%3}, {%4,%5,%6,%7}, {%8,%9}, {%0,%1,%2,%3};"
        : "+f"(c[0]), "+f"(c[1]), "+f"(c[2]), "+f"(c[3])
        : "r"(a[0]), "r"(a[1]), "r"(a[2]), "r"(a[3]), "r"(b[0]), "r"(b[1]));
}

// ---------------- conv3x3/1x1 as implicit GEMM on tensor cores (tf32) -------
// Block: 256 threads (8 warps). Tile: 64 co x 128 px (2 image rows x 64 cols).
// Warp tile: 32 co x 32 px = 2 m-frags (m16) x 4 n-frags (n8). K-chunk: 8 ch.
// Smem interleave: slot 2t holds channel t, slot 2t+1 holds channel t+4, so
// every A / B fragment pair is one conflict-free LDS.64.
template<int KS, bool CONCAT, int ACT>
__global__ __launch_bounds__(256) void conv_mma(
    const float* __restrict__ in0, const float* __restrict__ in1,
    const float* __restrict__ wgt, const float* __restrict__ bias,
    float* __restrict__ out, int Cin, int C0, int Cout)
{
    constexpr int HALO = KS / 2;
    constexpr int ROWS = 2 + 2 * HALO;     // smem image rows
    constexpr int SC   = 64 + 2 * HALO;    // smem image cols
    constexpr int NT   = KS * KS;          // taps
    __shared__ unsigned Xs[ROWS][SC][8];   // [row][col][interleaved ch]
    __shared__ unsigned Wsm[NT][64][8];    // [tap][co][interleaved ch]

    const int tid   = threadIdx.x;
    const int warp  = tid >> 5;
    const int lane  = tid & 31;
    const int g     = lane >> 2;           // 0..7
    const int t     = lane & 3;            // 0..3
    const int mwarp = warp >> 2;           // 0..1 -> co half
    const int nwarp = warp & 3;            // 0..3
    const int rsel  = nwarp >> 1;          // image row within tile (0/1)
    const int cb    = (nwarp & 1) * 32;    // col base within row
    const int h0    = blockIdx.x * 2;
    const int cot   = blockIdx.y;
    const int b     = blockIdx.z;

    const float* base0 = in0 + (size_t)b * C0 * PIX;
    const float* base1 = CONCAT ? (in1 + (size_t)b * (Cin - C0) * PIX) : nullptr;

    float acc[2][4][4];
    #pragma unroll
    for (int mi = 0; mi < 2; mi++)
        #pragma unroll
        for (int ni = 0; ni < 4; ni++)
            #pragma unroll
            for (int k = 0; k < 4; k++) acc[mi][ni][k] = 0.f;

    for (int cig = 0; cig < Cin; cig += 8) {
        // ---- weights: Wsm[tap][co][2tc] = ch tc, [2tc+1] = ch tc+4 ----
        // idx = (tap*64 + co)*4 + tc  -> consecutive lanes write consecutive
        // 8B words (conflict-free STS.64)
        for (int idx = tid; idx < 64 * 4 * NT; idx += 256) {
            int tc  = idx & 3;
            int co  = (idx >> 2) & 63;
            int tap = idx >> 8;
            size_t wb = ((size_t)(cot * 64 + co) * Cin + cig + tc) * NT + tap;
            unsigned w0 = f2tf32(wgt[wb]);
            unsigned w1 = f2tf32(wgt[wb + 4 * NT]);
            *(uint2*)&Wsm[tap][co][2 * tc] = make_uint2(w0, w1);
        }
        // ---- input tile (+halo, zero pad): Xs[r][c][2tc]=ch tc, [2tc+1]=tc+4
        for (int idx = tid; idx < 4 * ROWS * SC; idx += 256) {
            int tc  = idx & 3;
            int rc  = idx >> 2;
            int r   = rc / SC;
            int c   = rc - r * SC;
            int h   = h0 - HALO + r;
            int w   = c - HALO;
            float v0 = 0.f, v1 = 0.f;
            if (h >= 0 && h < 64 && w >= 0 && w < 64) {
                int ch0 = cig + tc, ch1 = cig + tc + 4;
                const float* p0 = (CONCAT && ch0 >= C0)
                                      ? (base1 + (size_t)(ch0 - C0) * PIX)
                                      : (base0 + (size_t)ch0 * PIX);
                const float* p1 = (CONCAT && ch1 >= C0)
                                      ? (base1 + (size_t)(ch1 - C0) * PIX)
                                      : (base0 + (size_t)ch1 * PIX);
                v0 = p0[h * 64 + w];
                v1 = p1[h * 64 + w];
            }
            *(uint2*)&Xs[r][c][2 * tc] = make_uint2(f2tf32(v0), f2tf32(v1));
        }
        __syncthreads();

        #pragma unroll
        for (int tap = 0; tap < NT; tap++) {
            const int ky = tap / KS, kx = tap % KS;
            unsigned a[2][4], bf[4][2];
            #pragma unroll
            for (int mi = 0; mi < 2; mi++) {
                int cor = mwarp * 32 + mi * 16 + g;
                uint2 lo = *(const uint2*)&Wsm[tap][cor][2 * t];
                uint2 hi = *(const uint2*)&Wsm[tap][cor + 8][2 * t];
                a[mi][0] = lo.x; a[mi][2] = lo.y;   // k=t, k=t+4 (row g)
                a[mi][1] = hi.x; a[mi][3] = hi.y;   // row g+8
            }
            #pragma unroll
            for (int ni = 0; ni < 4; ni++) {
                uint2 bv = *(const uint2*)&Xs[rsel + ky][cb + ni * 8 + g + kx][2 * t];
                bf[ni][0] = bv.x; bf[ni][1] = bv.y; // k=t, k=t+4 (col g)
            }
            #pragma unroll
            for (int mi = 0; mi < 2; mi++)
                #pragma unroll
                for (int ni = 0; ni < 4; ni++)
                    mma_tf32(acc[mi][ni], a[mi], bf[ni]);
        }
        __syncthreads();
    }

    // ---- epilogue: C frag (row g/g+8, cols 2t, 2t+1) ----
    const int hrow = h0 + rsel;
    #pragma unroll
    for (int mi = 0; mi < 2; mi++) {
        int co0 = cot * 64 + mwarp * 32 + mi * 16 + g;
        float bv0 = bias[co0];
        float bv8 = bias[co0 + 8];
        #pragma unroll
        for (int ni = 0; ni < 4; ni++) {
            int wcol = cb + ni * 8 + 2 * t;
            float v0 = acc[mi][ni][0] + bv0;
            float v1 = acc[mi][ni][1] + bv0;
            float v2 = acc[mi][ni][2] + bv8;
            float v3 = acc[mi][ni][3] + bv8;
            if (ACT == 1) {
                v0 = gelu_exact(v0); v1 = gelu_exact(v1);
                v2 = gelu_exact(v2); v3 = gelu_exact(v3);
            }
            *(float2*)&out[(((size_t)b * Cout + co0) * 64 + hrow) * 64 + wcol] =
                make_float2(v0, v1);
            *(float2*)&out[(((size_t)b * Cout + co0 + 8) * 64 + hrow) * 64 + wcol] =
                make_float2(v2, v3);
        }
    }
}

// ---------------- box conv2 (64->4 1x1) + sigmoid ----------------
__global__ __launch_bounds__(256) void box_conv2(const float* __restrict__ w2,
                                                 const float* __restrict__ b2)
{
    __shared__ float ws[256];
    int tid = threadIdx.x;
    ws[tid] = w2[tid];                       // [4][64]
    __syncthreads();
    int b = blockIdx.y;
    int p = blockIdx.x * 256 + tid;
    const float* in = g_t1 + (size_t)b * 64 * PIX;
    float acc[4] = {b2[0], b2[1], b2[2], b2[3]};
    for (int ci = 0; ci < 64; ci++) {
        float xv = in[(size_t)ci * PIX + p];
        #pragma unroll
        for (int co = 0; co < 4; co++) acc[co] = fmaf(ws[co * 64 + ci], xv, acc[co]);
    }
    #pragma unroll
    for (int co = 0; co < 4; co++)
        g_boxes[((size_t)b * 4 + co) * PIX + p] = 1.0f / (1.0f + expf(-acc[co]));
}

// ---------------- edge conv1 (4->64 3x3) ----------------
__global__ __launch_bounds__(256) void edge_conv1(const float* __restrict__ w1,
                                                  const float* __restrict__ b1)
{
    __shared__ float ws[8][4][9];
    __shared__ float bs[8];
    int tid = threadIdx.x;
    int cg = blockIdx.x;                     // co group (8 channels)
    int b  = blockIdx.y;
    for (int idx = tid; idx < 288; idx += 256) {
        int j = idx / 36, rem = idx % 36;
        int ci = rem / 9, t = rem % 9;
        ws[j][ci][t] = w1[((cg * 8 + j) * 4 + ci) * 9 + t];
    }
    if (tid < 8) bs[tid] = b1[cg * 8 + tid];
    __syncthreads();
    const float* bx = g_boxes + (size_t)b * 4 * PIX;
    for (int px = tid; px < PIX; px += 256) {
        int h = px >> 6, w = px & 63;
        float acc[8];
        #pragma unroll
        for (int j = 0; j < 8; j++) acc[j] = bs[j];
        #pragma unroll
        for (int ky = 0; ky < 3; ky++) {
            int hh = h + ky - 1;
            if (hh < 0 || hh >= 64) continue;
            #pragma unroll
            for (int kx = 0; kx < 3; kx++) {
                int ww = w + kx - 1;
                if (ww < 0 || ww >= 64) continue;
                #pragma unroll
                for (int ci = 0; ci < 4; ci++) {
                    float xv = bx[(size_t)ci * PIX + hh * 64 + ww];
                    #pragma unroll
                    for (int j = 0; j < 8; j++)
                        acc[j] = fmaf(ws[j][ci][ky * 3 + kx], xv, acc[j]);
                }
            }
        }
        #pragma unroll
        for (int j = 0; j < 8; j++)
            g_e1[((size_t)b * 64 + cg * 8 + j) * PIX + px] = acc[j];
    }
}

// ---------------- GroupNorm(8,64) + GELU (in place on g_e1) ----------------
__global__ __launch_bounds__(256) void gn_gelu(const float* __restrict__ gam,
                                               const float* __restrict__ bet)
{
    int blk = blockIdx.x;
    int b = blk >> 3, g = blk & 7;
    float* buf = g_e1 + ((size_t)b * 64 + g * 8) * PIX;
    __shared__ float red[256], red2[256];
    __shared__ float sm, si;
    float s = 0.f, sq = 0.f;
    for (int t = threadIdx.x; t < 8 * PIX; t += 256) {
        float v = buf[t]; s += v; sq += v * v;
    }
    red[threadIdx.x] = s; red2[threadIdx.x] = sq;
    __syncthreads();
    for (int o = 128; o > 0; o >>= 1) {
        if (threadIdx.x < o) {
            red[threadIdx.x]  += red[threadIdx.x + o];
            red2[threadIdx.x] += red2[threadIdx.x + o];
        }
        __syncthreads();
    }
    if (threadIdx.x == 0) {
        float m = red[0] / (8.f * PIX);
        float var = red2[0] / (8.f * PIX) - m * m;
        sm = m; si = rsqrtf(var + 1e-5f);
    }
    __syncthreads();
    float m = sm, istd = si;
    for (int t = threadIdx.x; t < 8 * PIX; t += 256) {
        int cl = t >> 12;
        int c = g * 8 + cl;
        float v = (buf[t] - m) * istd * gam[c] + bet[c];
        buf[t] = gelu_exact(v);
    }
}

// ---------------- edge conv2 (64->8 1x1) ----------------
__global__ __launch_bounds__(256) void edge_conv2(const float* __restrict__ w2,
                                                  const float* __restrict__ b2)
{
    __shared__ float ws[512];
    int tid = threadIdx.x;
    ws[tid] = w2[tid];
    ws[tid + 256] = w2[tid + 256];
    __syncthreads();
    int b = blockIdx.y;
    int p = blockIdx.x * 256 + tid;
    const float* in = g_e1 + (size_t)b * 64 * PIX;
    float acc[8];
    #pragma unroll
    for (int co = 0; co < 8; co++) acc[co] = b2[co];
    for (int ci = 0; ci < 64; ci++) {
        float xv = in[(size_t)ci * PIX + p];
        #pragma unroll
        for (int co = 0; co < 8; co++) acc[co] = fmaf(ws[co * 64 + ci], xv, acc[co]);
    }
    #pragma unroll
    for (int co = 0; co < 8; co++)
        g_edge[((size_t)b * 8 + co) * PIX + p] = acc[co];
}

// ---------------- attention: S = scale*Q_i^T K_i + edge ----------------
__global__ __launch_bounds__(256) void attn_qk()
{
    __shared__ float Qs[64 * 64];
    __shared__ float Ks[64 * 64];
    int i = blockIdx.x, h = blockIdx.y, b = blockIdx.z;
    int tid = threadIdx.x;
    const float* qp = g_qkv + ((size_t)b * 1536 + h * 64 + i) * PIX;
    const float* kp = g_qkv + ((size_t)b * 1536 + 512 + h * 64 + i) * PIX;
    float4* Q4 = (float4*)Qs;
    float4* K4 = (float4*)Ks;
    for (int t = tid; t < 1024; t += 256) {
        Q4[t] = ((const float4*)qp)[t];
        K4[t] = ((const float4*)kp)[t];
    }
    __syncthreads();
    int wr = (tid >> 4) << 2;   // attn row (w) base
    int wc = (tid & 15) << 2;   // attn col (W') base
    float acc[4][4];
    #pragma unroll
    for (int a = 0; a < 4; a++)
        #pragma unroll
        for (int j = 0; j < 4; j++) acc[a][j] = 0.f;
    for (int d = 0; d < 64; d++) {
        float4 qv = Q4[d * 16 + (wr >> 2)];
        float4 kv = K4[d * 16 + (wc >> 2)];
        float q[4] = {qv.x, qv.y, qv.z, qv.w};
        float k[4] = {kv.x, kv.y, kv.z, kv.w};
        #pragma unroll
        for (int a = 0; a < 4; a++)
            #pragma unroll
            for (int j = 0; j < 4; j++)
                acc[a][j] = fmaf(q[a], k[j], acc[a][j]);
    }
    float* op = g_attn + ((size_t)(b * 8 + h) * 64 + i) * PIX;
    const float* ep = g_edge + (size_t)(b * 8 + h) * PIX + i * 64;
    #pragma unroll
    for (int a = 0; a < 4; a++) {
        float e = ep[wr + a];
        float4 o;
        o.x = acc[a][0] * 0.125f + e;
        o.y = acc[a][1] * 0.125f + e;
        o.z = acc[a][2] * 0.125f + e;
        o.w = acc[a][3] * 0.125f + e;
        *(float4*)(op + (wr + a) * 64 + wc) = o;
    }
}

// ---------------- softmax over i (HD axis) ----------------
__global__ __launch_bounds__(256) void attn_softmax()
{
    int w4 = blockIdx.x, h = blockIdx.y, b = blockIdx.z;
    int tid = threadIdx.x;
    int w  = w4 * 4 + (tid >> 6);
    int wp = tid & 63;
    float* base = g_attn + (size_t)(b * 8 + h) * 64 * PIX + w * 64 + wp;
    float v[64];
    #pragma unroll
    for (int i = 0; i < 64; i++) v[i] = base[(size_t)i * PIX];
    float m = v[0];
    #pragma unroll
    for (int i = 1; i < 64; i++) m = fmaxf(m, v[i]);
    float s = 0.f;
    #pragma unroll
    for (int i = 0; i < 64; i++) { v[i] = expf(v[i] - m); s += v[i]; }
    float r = 1.0f / s;
    #pragma unroll
    for (int i = 0; i < 64; i++) base[(size_t)i * PIX] = v[i] * r;
}

// ---------------- agg_i = V_i @ A_i^T ----------------
__global__ __launch_bounds__(256) void attn_agg()
{
    __shared__ float At[64 * 68];   // At[W][w] = attn[w][W]
    __shared__ float Vt[64 * 68];   // Vt[W][d] = v[d][W]
    int i = blockIdx.x, h = blockIdx.y, b = blockIdx.z;
    int tid = threadIdx.x;
    const float* ap = g_attn + ((size_t)(b * 8 + h) * 64 + i) * PIX;
    const float* vp = g_qkv + ((size_t)b * 1536 + 1024 + h * 64 + i) * PIX;
    for (int t = tid; t < 4096; t += 256) {
        int r = t >> 6, c = t & 63;
        At[c * 68 + r] = ap[t];
        Vt[c * 68 + r] = vp[t];
    }
    __syncthreads();
    int d0 = (tid >> 4) << 2;
    int w0 = (tid & 15) << 2;
    float acc[4][4];
    #pragma unroll
    for (int a = 0; a < 4; a++)
        #pragma unroll
        for (int j = 0; j < 4; j++) acc[a][j] = 0.f;
    for (int W = 0; W < 64; W++) {
        float4 vv = *(const float4*)(Vt + W * 68 + d0);
        float4 av = *(const float4*)(At + W * 68 + w0);
        float vd[4] = {vv.x, vv.y, vv.z, vv.w};
        float aw[4] = {av.x, av.y, av.z, av.w};
        #pragma unroll
        for (int a = 0; a < 4; a++)
            #pragma unroll
            for (int j = 0; j < 4; j++)
                acc[a][j] = fmaf(vd[a], aw[j], acc[a][j]);
    }
    float* op = g_agg + ((size_t)b * 512 + h * 64 + i) * PIX;
    #pragma unroll
    for (int a = 0; a < 4; a++) {
        float4 o = {acc[a][0], acc[a][1], acc[a][2], acc[a][3]};
        *(float4*)(op + (d0 + a) * 64 + w0) = o;
    }
}

// ---------------- BatchNorm stats (per channel over B,H,W) ----------------
__global__ __launch_bounds__(256) void bn_stats()
{
    int c = blockIdx.x;
    __shared__ float red[256], red2[256];
    float s = 0.f, sq = 0.f;
    for (int t = threadIdx.x; t < 8 * PIX; t += 256) {
        int b = t >> 12, p = t & 4095;
        float v = g_y[((size_t)b * 512 + c) * PIX + p];
        s += v; sq += v * v;
    }
    red[threadIdx.x] = s; red2[threadIdx.x] = sq;
    __syncthreads();
    for (int o = 128; o > 0; o >>= 1) {
        if (threadIdx.x < o) {
            red[threadIdx.x]  += red[threadIdx.x + o];
            red2[threadIdx.x] += red2[threadIdx.x + o];
        }
        __syncthreads();
    }
    if (threadIdx.x == 0) {
        float m = red[0] / (8.f * PIX);
        float var = red2[0] / (8.f * PIX) - m * m;
        g_mean[c] = m;
        g_istd[c] = rsqrtf(var + 1e-5f);
    }
}

// ---------------- BN apply + SiLU -> d_out ----------------
__global__ __launch_bounds__(256) void bn_silu(const float* __restrict__ gam,
                                               const float* __restrict__ bet,
                                               float* __restrict__ out)
{
    size_t idx = (size_t)blockIdx.x * 256 + threadIdx.x;
    int c = (int)((idx >> 12) & 511);
    float v = g_y[idx];
    float yn = (v - g_mean[c]) * g_istd[c] * gam[c] + bet[c];
    out[idx] = yn / (1.0f + expf(-yn));
}

// ---------------- launch ----------------
extern "C" void kernel_launch(void* const* d_in, const int* in_sizes, int n_in,
                              void* d_out, int out_size)
{
    const float* x       = (const float*)d_in[0];
    const float* box_w1  = (const float*)d_in[1];
    const float* box_b1  = (const float*)d_in[2];
    const float* box_w2  = (const float*)d_in[3];
    const float* box_b2  = (const float*)d_in[4];
    const float* edge_w1 = (const float*)d_in[5];
    const float* edge_b1 = (const float*)d_in[6];
    const float* gn_g    = (const float*)d_in[7];
    const float* gn_b    = (const float*)d_in[8];
    const float* edge_w2 = (const float*)d_in[9];
    const float* edge_b2 = (const float*)d_in[10];
    const float* qkv_w   = (const float*)d_in[11];
    const float* qkv_b   = (const float*)d_in[12];
    const float* fus_w   = (const float*)d_in[13];
    const float* fus_b   = (const float*)d_in[14];
    const float* bn_g    = (const float*)d_in[15];
    const float* bn_b    = (const float*)d_in[16];
    float* out = (float*)d_out;

    float *t1, *qkv, *agg, *y;
    cudaGetSymbolAddress((void**)&t1,  g_t1);
    cudaGetSymbolAddress((void**)&qkv, g_qkv);
    cudaGetSymbolAddress((void**)&agg, g_agg);
    cudaGetSymbolAddress((void**)&y,   g_y);

    // box net: conv3x3(512->64)+GELU, conv1x1(64->4)+sigmoid
    conv_mma<3, false, 1><<<dim3(32, 1, 8), 256>>>(x, nullptr, box_w1, box_b1,
                                                   t1, 512, 512, 64);
    box_conv2<<<dim3(16, 8), 256>>>(box_w2, box_b2);

    // edge net: conv3x3(4->64), GN+GELU, conv1x1(64->8)
    edge_conv1<<<dim3(8, 8), 256>>>(edge_w1, edge_b1);
    gn_gelu<<<64, 256>>>(gn_g, gn_b);
    edge_conv2<<<dim3(16, 8), 256>>>(edge_w2, edge_b2);

    // qkv 1x1 conv (512->1536)
    conv_mma<1, false, 0><<<dim3(32, 24, 8), 256>>>(x, nullptr, qkv_w, qkv_b,
                                                    qkv, 512, 512, 1536);

    // attention
    attn_qk<<<dim3(64, 8, 8), 256>>>();
    attn_softmax<<<dim3(16, 8, 8), 256>>>();
    attn_agg<<<dim3(64, 8, 8), 256>>>();

    // fusion conv3x3 (concat(x, agg): 1024->512)
    conv_mma<3, true, 0><<<dim3(32, 8, 8), 256>>>(x, agg, fus_w, fus_b,
                                                  y, 1024, 512, 512);

    // BatchNorm (training stats) + SiLU
    bn_stats<<<512, 256>>>();
    bn_silu<<<65536, 256>>>(bn_g, bn_b, out);
}